// round 16
// baseline (speedup 1.0000x reference)
#include <cuda_runtime.h>
#include <cuda_bf16.h>

// CumAvgPool1d: y[..., t] = cumsum(x)[..., t] / (t+1)
// x: (8, 512, 16384) fp32 -> 4096 rows of T=16384.
//
// R15: R14 (CTA of 8 warps, 256-elem chunks, depth-2 ring, publish-early
// butterfly totals + HW-barrier relay) extended to TWO memory-contiguous
// rows per CTA. Grid 2048 -> ~3.5 waves instead of 7; the prefetch ring
// stays full across the row boundary (the pair is one contiguous 128KB
// region), eliminating per-row cold prologs and halving wave transitions.
// Carry/divisor bookkeeping resets at the row boundary (k==8), which is
// compile-time in the fully unrolled 16-round loop.

constexpr int T_LEN  = 16384;
constexpr int T_F4   = T_LEN / 4;            // 4096 float4 per row
constexpr int CHUNK_F4 = 64;                 // 256 elems per chunk
constexpr int WARPS  = 8;
constexpr int THREADS = WARPS * 32;          // 256
constexpr int ROUNDS_PER_ROW = T_F4 / CHUNK_F4 / WARPS;   // 8
constexpr int ROWS_PER_CTA = 2;
constexpr int ROUNDS = ROUNDS_PER_ROW * ROWS_PER_CTA;     // 16
constexpr int PAIR_F4 = T_F4 * ROWS_PER_CTA;              // 8192

__global__ void __launch_bounds__(THREADS)
cumavg_kernel(const float4* __restrict__ x, float4* __restrict__ y)
{
    __shared__ float relay[WARPS * ROUNDS_PER_ROW];   // 64 slots, reused per row

    const int tid  = threadIdx.x;
    const int lane = tid & 31;
    const int warp = tid >> 5;

    const size_t pbase = (size_t)blockIdx.x * PAIR_F4;
    const float4* px = x + pbase;
    float4*       py = y + pbase;

    // depth-2 prefetch ring over the pair's chunk sequence (stride 8 chunks)
    float4 ra4[2], rb4[2];
    {
        const int c0 = warp;
        const int c1 = warp + WARPS;
        ra4[0] = __ldcs(px + c0 * CHUNK_F4 + lane);
        rb4[0] = __ldcs(px + c0 * CHUNK_F4 + 32 + lane);
        ra4[1] = __ldcs(px + c1 * CHUNK_F4 + lane);
        rb4[1] = __ldcs(px + c1 * CHUNK_F4 + 32 + lane);
    }

    float carry = 0.0f;
    // divisor base (exact integer floats): within-row chunk cr => t0 = cr*256 + lane*4
    float tb = (float)(warp * 256 + lane * 4);

    #pragma unroll
    for (int k = 0; k < ROUNDS; ++k) {
        const int c = warp + WARPS * k;     // chunk index within the row pair

        // row boundary: reset scan bookkeeping (compile-time branch)
        if (k == ROUNDS_PER_ROW) {
            carry = 0.0f;
            tb = (float)(warp * 256 + lane * 4);
        }

        float4 a = ra4[k & 1];
        float4 b = rb4[k & 1];
        if (k + 2 < ROUNDS) {
            const int cn = c + 2 * WARPS;   // contiguous across the row boundary
            ra4[k & 1] = __ldcs(px + cn * CHUNK_F4 + lane);
            rb4[k & 1] = __ldcs(px + cn * CHUNK_F4 + 32 + lane);
        }

        // ---- fast path to publish: FADD-tree lane sum + butterfly ----
        float lsum = ((a.x + a.y) + (a.z + a.w)) + ((b.x + b.y) + (b.z + b.w));
        float ct = lsum;
        #pragma unroll
        for (int d = 16; d >= 1; d >>= 1)
            ct += __shfl_xor_sync(0xffffffffu, ct, d);
        const int rslot = c & (WARPS * ROUNDS_PER_ROW - 1);   // 64-slot reuse
        if (lane == 0) relay[rslot] = ct;

        // ---- prefix scans (overlap other warps' publish window) ----
        float rA = a.x;  a.x = rA;
        rA += a.y;       a.y = rA;
        rA += a.z;       a.z = rA;
        rA += a.w;       a.w = rA;

        float rB = b.x;  b.x = rB;
        rB += b.y;       b.y = rB;
        rB += b.z;       b.z = rB;
        rB += b.w;       b.w = rB;

        float wA = rA, wB = rB;
        #pragma unroll
        for (int d = 1; d < 32; d <<= 1) {
            float nA = __shfl_up_sync(0xffffffffu, wA, d);
            float nB = __shfl_up_sync(0xffffffffu, wB, d);
            if (lane >= d) { wA += nA; wB += nB; }
        }
        const float totalA = __shfl_sync(0xffffffffu, wA, 31);

        __syncthreads();

        // combine the round's 8 totals: width-8 inclusive shuffle scan
        const int base = (rslot & ~(WARPS - 1));
        float s = relay[base + (lane & (WARPS - 1))];
        #pragma unroll
        for (int d = 1; d < WARPS; d <<= 1) {
            float n = __shfl_up_sync(0xffffffffu, s, d, WARPS);
            if ((lane & (WARPS - 1)) >= d) s += n;
        }
        const float all = __shfl_sync(0xffffffffu, s, WARPS - 1, WARPS);
        const float pw  = __shfl_sync(0xffffffffu, s, (warp == 0 ? 0 : warp - 1), WARPS);
        const float P   = carry + (warp ? pw : 0.0f);
        carry += all;

        const float offA = P + (wA - rA);            // exclusive prefix, A half
        const float offB = P + totalA + (wB - rB);   // exclusive prefix, B half

        // y[t] = (off + local) / (t+1); divisors via float adds (exact ints)
        float4 o;
        o.x = (offA + a.x) * __fdividef(1.0f, tb + 1.0f);
        o.y = (offA + a.y) * __fdividef(1.0f, tb + 2.0f);
        o.z = (offA + a.z) * __fdividef(1.0f, tb + 3.0f);
        o.w = (offA + a.w) * __fdividef(1.0f, tb + 4.0f);
        __stcs(py + c * CHUNK_F4 + lane, o);

        o.x = (offB + b.x) * __fdividef(1.0f, tb + 129.0f);
        o.y = (offB + b.y) * __fdividef(1.0f, tb + 130.0f);
        o.z = (offB + b.z) * __fdividef(1.0f, tb + 131.0f);
        o.w = (offB + b.w) * __fdividef(1.0f, tb + 132.0f);
        __stcs(py + c * CHUNK_F4 + 32 + lane, o);

        tb += (float)(WARPS * 256);   // next owned chunk is 2048 elems ahead
    }
}

extern "C" void kernel_launch(void* const* d_in, const int* in_sizes, int n_in,
                              void* d_out, int out_size)
{
    const float* x = (const float*)d_in[0];
    float*       y = (float*)d_out;
    const int total = in_sizes[0];
    const int rows  = total / T_LEN;             // 4096 for the reference shape
    const int ctas  = rows / ROWS_PER_CTA;       // 2048

    cumavg_kernel<<<ctas, THREADS>>>((const float4*)x, (float4*)y);
}

// round 17
// speedup vs baseline: 1.6886x; 1.6886x over previous
#include <cuda_runtime.h>
#include <cuda_bf16.h>

// CumAvgPool1d: y[..., t] = cumsum(x)[..., t] / (t+1)
// x: (8, 512, 16384) fp32 -> 4096 rows of T=16384.
//
// R16: row-pairing (R15's idea) with register pressure CONTROLLED.
// Body identical to R14 (8 warps, 256-elem chunks, depth-2 ring,
// publish-early butterfly totals + HW-barrier relay, 60 regs), but each
// CTA processes 2 memory-contiguous rows in a 16-round loop with
// #pragma unroll 2 (R11/R14's proven unroll window -- NOT full unroll,
// which blew regs to 138 in R15). Row-boundary carry/divisor reset is a
// cheap runtime predicate. Grid 2048 -> ~3.5 waves; ring stays full across
// the contiguous row boundary (no per-row cold prolog).

constexpr int T_LEN  = 16384;
constexpr int T_F4   = T_LEN / 4;            // 4096 float4 per row
constexpr int CHUNK_F4 = 64;                 // 256 elems per chunk
constexpr int WARPS  = 8;
constexpr int THREADS = WARPS * 32;          // 256
constexpr int ROUNDS_PER_ROW = T_F4 / CHUNK_F4 / WARPS;   // 8
constexpr int ROWS_PER_CTA = 2;
constexpr int ROUNDS = ROUNDS_PER_ROW * ROWS_PER_CTA;     // 16
constexpr int PAIR_F4 = T_F4 * ROWS_PER_CTA;              // 8192

__global__ void __launch_bounds__(THREADS)
cumavg_kernel(const float4* __restrict__ x, float4* __restrict__ y)
{
    __shared__ float relay[WARPS];            // one slot per warp, reused per round

    const int tid  = threadIdx.x;
    const int lane = tid & 31;
    const int warp = tid >> 5;

    const size_t pbase = (size_t)blockIdx.x * PAIR_F4;
    const float4* px = x + pbase;
    float4*       py = y + pbase;

    // depth-2 prefetch ring over the pair's chunk sequence (stride 8 chunks)
    float4 ra4[2], rb4[2];
    {
        ra4[0] = __ldcs(px + warp * CHUNK_F4 + lane);
        rb4[0] = __ldcs(px + warp * CHUNK_F4 + 32 + lane);
        ra4[1] = __ldcs(px + (warp + WARPS) * CHUNK_F4 + lane);
        rb4[1] = __ldcs(px + (warp + WARPS) * CHUNK_F4 + 32 + lane);
    }

    float carry = 0.0f;
    // divisor base (exact integer floats): within-row chunk cr => t0 = cr*256 + lane*4
    const float tb0 = (float)(warp * 256 + lane * 4);
    float tb = tb0;

    #pragma unroll 2
    for (int k = 0; k < ROUNDS; ++k) {
        const int c = warp + WARPS * k;     // chunk index within the row pair

        // row boundary: reset scan bookkeeping (cheap predicated ops)
        if (k == ROUNDS_PER_ROW) { carry = 0.0f; tb = tb0; }

        float4 a = ra4[k & 1];
        float4 b = rb4[k & 1];
        if (k + 2 < ROUNDS) {
            const int cn = c + 2 * WARPS;   // contiguous across the row boundary
            ra4[k & 1] = __ldcs(px + cn * CHUNK_F4 + lane);
            rb4[k & 1] = __ldcs(px + cn * CHUNK_F4 + 32 + lane);
        }

        // ---- fast path to publish: FADD-tree lane sum + butterfly ----
        float lsum = ((a.x + a.y) + (a.z + a.w)) + ((b.x + b.y) + (b.z + b.w));
        float ct = lsum;
        #pragma unroll
        for (int d = 16; d >= 1; d >>= 1)
            ct += __shfl_xor_sync(0xffffffffu, ct, d);
        if (lane == 0) relay[warp] = ct;

        // ---- prefix scans (overlap other warps' publish window) ----
        float rA = a.x;  a.x = rA;
        rA += a.y;       a.y = rA;
        rA += a.z;       a.z = rA;
        rA += a.w;       a.w = rA;

        float rB = b.x;  b.x = rB;
        rB += b.y;       b.y = rB;
        rB += b.z;       b.z = rB;
        rB += b.w;       b.w = rB;

        float wA = rA, wB = rB;
        #pragma unroll
        for (int d = 1; d < 32; d <<= 1) {
            float nA = __shfl_up_sync(0xffffffffu, wA, d);
            float nB = __shfl_up_sync(0xffffffffu, wB, d);
            if (lane >= d) { wA += nA; wB += nB; }
        }
        const float totalA = __shfl_sync(0xffffffffu, wA, 31);

        __syncthreads();

        // combine the round's 8 totals: width-8 inclusive shuffle scan
        float s = relay[lane & (WARPS - 1)];
        #pragma unroll
        for (int d = 1; d < WARPS; d <<= 1) {
            float n = __shfl_up_sync(0xffffffffu, s, d, WARPS);
            if ((lane & (WARPS - 1)) >= d) s += n;
        }
        const float all = __shfl_sync(0xffffffffu, s, WARPS - 1, WARPS);
        const float pw  = __shfl_sync(0xffffffffu, s, (warp == 0 ? 0 : warp - 1), WARPS);
        const float P   = carry + (warp ? pw : 0.0f);
        carry += all;

        // barrier before next round's publish would overwrite relay;
        // the next __syncthreads at loop top serves -- but relay is written
        // pre-barrier next round, so we need the second barrier here:
        __syncthreads();

        const float offA = P + (wA - rA);            // exclusive prefix, A half
        const float offB = P + totalA + (wB - rB);   // exclusive prefix, B half

        // y[t] = (off + local) / (t+1); divisors via float adds (exact ints)
        float4 o;
        o.x = (offA + a.x) * __fdividef(1.0f, tb + 1.0f);
        o.y = (offA + a.y) * __fdividef(1.0f, tb + 2.0f);
        o.z = (offA + a.z) * __fdividef(1.0f, tb + 3.0f);
        o.w = (offA + a.w) * __fdividef(1.0f, tb + 4.0f);
        __stcs(py + c * CHUNK_F4 + lane, o);

        o.x = (offB + b.x) * __fdividef(1.0f, tb + 129.0f);
        o.y = (offB + b.y) * __fdividef(1.0f, tb + 130.0f);
        o.z = (offB + b.z) * __fdividef(1.0f, tb + 131.0f);
        o.w = (offB + b.w) * __fdividef(1.0f, tb + 132.0f);
        __stcs(py + c * CHUNK_F4 + 32 + lane, o);

        tb += (float)(WARPS * 256);   // next owned chunk is 2048 elems ahead
    }
}

extern "C" void kernel_launch(void* const* d_in, const int* in_sizes, int n_in,
                              void* d_out, int out_size)
{
    const float* x = (const float*)d_in[0];
    float*       y = (float*)d_out;
    const int total = in_sizes[0];
    const int rows  = total / T_LEN;             // 4096 for the reference shape
    const int ctas  = rows / ROWS_PER_CTA;       // 2048

    cumavg_kernel<<<ctas, THREADS>>>((const float4*)x, (float4*)y);
}